// round 1
// baseline (speedup 1.0000x reference)
#include <cuda_runtime.h>
#include <cuda_bf16.h>

// Problem constants (fixed by the reference):
//   VOXEL_SIZE = (0.16, 0.16, 4.0), PC_RANGE = (0, -39.68, -3, 69.12, 39.68, 1)
//   GRID = (432, 496, 1), MAX_VOX = 160000, C = 4
#define GX 432
#define GY 496
#define GZ 1
#define TOTAL_CELLS (GX * GY * GZ)   // 214272
#define MAX_VOX 160000
#define CPB 1024                     // cells per scan block
#define NBLK ((TOTAL_CELLS + CPB - 1) / CPB)  // 210

// Scratch (allocation-free rule: __device__ globals)
__device__ float g_vsum[TOTAL_CELLS * 4];
__device__ int   g_vcnt[TOTAL_CELLS];
__device__ int   g_boff[NBLK];

// ---------------------------------------------------------------------------
// 1. Zero scratch + output
// ---------------------------------------------------------------------------
__global__ void k_zero(float* __restrict__ out) {
    int i = blockIdx.x * blockDim.x + threadIdx.x;
    int stride = gridDim.x * blockDim.x;
    for (int j = i; j < TOTAL_CELLS * 4; j += stride) g_vsum[j] = 0.0f;
    for (int j = i; j < TOTAL_CELLS; j += stride)     g_vcnt[j] = 0;
    for (int j = i; j < MAX_VOX * 4; j += stride)     out[j]    = 0.0f;
}

// ---------------------------------------------------------------------------
// 2. Accumulate: per point, find cell, atomically add features + count.
//    Cell computation must match jnp float32 exactly: (x - low) / vsz, floor.
// ---------------------------------------------------------------------------
__global__ void k_acc(const float* __restrict__ in, int N, int P) {
    int i = blockIdx.x * blockDim.x + threadIdx.x;
    if (i >= P) return;
    int b = i / N;
    int n = i - b * N;
    const float* p = in + (size_t)b * 4 * (size_t)N + n;
    float x = p[0];
    float y = p[(size_t)N];
    float z = p[2 * (size_t)N];
    float w = p[3 * (size_t)N];

    // IEEE single-precision division to match XLA bit-exactly at boundaries.
    float fx = floorf(__fdiv_rn(x - 0.0f,   0.16f));
    float fy = floorf(__fdiv_rn(y + 39.68f, 0.16f));
    float fz = floorf(__fdiv_rn(z + 3.0f,   4.0f));
    if (fx < 0.0f || fy < 0.0f || fz < 0.0f) return;
    int cx = (int)fx, cy = (int)fy, cz = (int)fz;
    if (cx >= GX || cy >= GY || cz >= GZ) return;

    int cell = (cz * GY + cy) * GX + cx;
    atomicAdd(&g_vcnt[cell], 1);
    atomicAdd(&g_vsum[cell * 4 + 0], x);
    atomicAdd(&g_vsum[cell * 4 + 1], y);
    atomicAdd(&g_vsum[cell * 4 + 2], z);
    atomicAdd(&g_vsum[cell * 4 + 3], w);
}

// ---------------------------------------------------------------------------
// 3. Per-block occupancy counts (block b covers cells [b*CPB, (b+1)*CPB))
// ---------------------------------------------------------------------------
__global__ void k_count() {
    __shared__ int sdata[32];
    int b = blockIdx.x;
    int t = threadIdx.x;
    int cell = b * CPB + t;
    int flag = (cell < TOTAL_CELLS) && (g_vcnt[cell] > 0);
    int v = flag;
    #pragma unroll
    for (int o = 16; o > 0; o >>= 1) v += __shfl_down_sync(0xFFFFFFFFu, v, o);
    if ((t & 31) == 0) sdata[t >> 5] = v;
    __syncthreads();
    if (t < 32) {
        int w = sdata[t];
        #pragma unroll
        for (int o = 16; o > 0; o >>= 1) w += __shfl_down_sync(0xFFFFFFFFu, w, o);
        if (t == 0) g_boff[b] = w;
    }
}

// ---------------------------------------------------------------------------
// 4. Exclusive scan of 210 block sums (single thread — trivial size)
// ---------------------------------------------------------------------------
__global__ void k_scan() {
    if (threadIdx.x == 0 && blockIdx.x == 0) {
        int acc = 0;
        for (int i = 0; i < NBLK; i++) {
            int v = g_boff[i];
            g_boff[i] = acc;
            acc += v;
        }
    }
}

// ---------------------------------------------------------------------------
// 5. Block-local exclusive scan -> seg id; write mean for seg < MAX_VOX
// ---------------------------------------------------------------------------
__global__ void k_write(float* __restrict__ out) {
    __shared__ int wsum[32];
    int b = blockIdx.x;
    int t = threadIdx.x;
    int lane = t & 31;
    int wid = t >> 5;
    int cell = b * CPB + t;
    int flag = (cell < TOTAL_CELLS) && (g_vcnt[cell] > 0);

    // inclusive warp scan of flags
    int v = flag;
    #pragma unroll
    for (int o = 1; o < 32; o <<= 1) {
        int nv = __shfl_up_sync(0xFFFFFFFFu, v, o);
        if (lane >= o) v += nv;
    }
    if (lane == 31) wsum[wid] = v;
    __syncthreads();
    if (wid == 0) {
        int w = wsum[lane];
        #pragma unroll
        for (int o = 1; o < 32; o <<= 1) {
            int nw = __shfl_up_sync(0xFFFFFFFFu, w, o);
            if (lane >= o) w += nw;
        }
        wsum[lane] = w;  // inclusive warp totals
    }
    __syncthreads();

    if (flag) {
        int excl = (v - flag) + (wid > 0 ? wsum[wid - 1] : 0);
        int seg = g_boff[b] + excl;
        if (seg < MAX_VOX) {
            int cnt = g_vcnt[cell];
            float fc = (float)cnt;
            float s0 = g_vsum[cell * 4 + 0];
            float s1 = g_vsum[cell * 4 + 1];
            float s2 = g_vsum[cell * 4 + 2];
            float s3 = g_vsum[cell * 4 + 3];
            out[seg * 4 + 0] = __fdiv_rn(s0, fc);
            out[seg * 4 + 1] = __fdiv_rn(s1, fc);
            out[seg * 4 + 2] = __fdiv_rn(s2, fc);
            out[seg * 4 + 3] = __fdiv_rn(s3, fc);
        }
    }
}

// ---------------------------------------------------------------------------
extern "C" void kernel_launch(void* const* d_in, const int* in_sizes, int n_in,
                              void* d_out, int out_size) {
    const float* in = (const float*)d_in[0];
    float* out = (float*)d_out;
    int total = in_sizes[0];       // B * C * N = 4 * 4 * 200000
    int N = total / 16;            // points per batch (B=4, C=4)
    int P = total / 4;             // total points

    k_zero<<<512, 256>>>(out);
    k_acc<<<(P + 255) / 256, 256>>>(in, N, P);
    k_count<<<NBLK, CPB>>>();
    k_scan<<<1, 32>>>();
    k_write<<<NBLK, CPB>>>(out);
}

// round 2
// speedup vs baseline: 1.7151x; 1.7151x over previous
#include <cuda_runtime.h>
#include <cuda_bf16.h>

// Problem constants (fixed by the reference):
//   VOXEL_SIZE = (0.16, 0.16, 4.0), PC_RANGE = (0, -39.68, -3, 69.12, 39.68, 1)
//   GRID = (432, 496, 1), MAX_VOX = 160000, C = 4
#define GX 432
#define GY 496
#define GZ 1
#define TOTAL_CELLS (GX * GY * GZ)   // 214272
#define MAX_VOX 160000
#define CPB 1024                     // cells per scan block
#define NBLK ((TOTAL_CELLS + CPB - 1) / CPB)  // 210

// Scratch (allocation-free rule: __device__ globals). float4 => 16B aligned
// for red.global.add.v4.f32.
__device__ float4 g_vsum[TOTAL_CELLS];
__device__ int    g_vcnt[TOTAL_CELLS];
__device__ int    g_boff[NBLK];

// ---------------------------------------------------------------------------
// 1. Zero scratch + output (vectorized)
// ---------------------------------------------------------------------------
__global__ void k_zero(float4* __restrict__ out4) {
    int i = blockIdx.x * blockDim.x + threadIdx.x;
    int stride = gridDim.x * blockDim.x;
    const float4 z4 = make_float4(0.f, 0.f, 0.f, 0.f);
    for (int j = i; j < TOTAL_CELLS; j += stride) g_vsum[j] = z4;
    for (int j = i; j < TOTAL_CELLS; j += stride) g_vcnt[j] = 0;
    for (int j = i; j < MAX_VOX; j += stride)     out4[j]   = z4;
}

// ---------------------------------------------------------------------------
// 2. Accumulate: per point, find cell, one v4 float reduction + one int
//    reduction. Cell computation matches jnp float32 exactly:
//    floor((x - low) / vsz) with IEEE round-to-nearest division.
// ---------------------------------------------------------------------------
__global__ void k_acc(const float* __restrict__ in, int N, int P) {
    int i = blockIdx.x * blockDim.x + threadIdx.x;
    if (i >= P) return;
    int b = i / N;
    int n = i - b * N;
    const float* p = in + (size_t)b * 4 * (size_t)N + n;
    float x = p[0];
    float y = p[(size_t)N];
    float z = p[2 * (size_t)N];
    float w = p[3 * (size_t)N];

    float fx = floorf(__fdiv_rn(x - 0.0f,   0.16f));
    float fy = floorf(__fdiv_rn(y + 39.68f, 0.16f));
    float fz = floorf(__fdiv_rn(z + 3.0f,   4.0f));
    if (fx < 0.0f || fy < 0.0f || fz < 0.0f) return;
    int cx = (int)fx, cy = (int)fy, cz = (int)fz;
    if (cx >= GX || cy >= GY || cz >= GZ) return;

    int cell = (cz * GY + cy) * GX + cx;

    // One 16B vector reduction instead of 4 scalar REDGs (sm_90+).
    float4* vp = &g_vsum[cell];
    asm volatile("red.global.add.v4.f32 [%0], {%1, %2, %3, %4};"
                 :: "l"(vp), "f"(x), "f"(y), "f"(z), "f"(w) : "memory");
    atomicAdd(&g_vcnt[cell], 1);
}

// ---------------------------------------------------------------------------
// 3. Per-block occupancy counts (block b covers cells [b*CPB, (b+1)*CPB))
// ---------------------------------------------------------------------------
__global__ void k_count() {
    __shared__ int sdata[32];
    int b = blockIdx.x;
    int t = threadIdx.x;
    int cell = b * CPB + t;
    int flag = (cell < TOTAL_CELLS) && (g_vcnt[cell] > 0);
    int v = flag;
    #pragma unroll
    for (int o = 16; o > 0; o >>= 1) v += __shfl_down_sync(0xFFFFFFFFu, v, o);
    if ((t & 31) == 0) sdata[t >> 5] = v;
    __syncthreads();
    if (t < 32) {
        int w = sdata[t];
        #pragma unroll
        for (int o = 16; o > 0; o >>= 1) w += __shfl_down_sync(0xFFFFFFFFu, w, o);
        if (t == 0) g_boff[b] = w;
    }
}

// ---------------------------------------------------------------------------
// 4. Exclusive scan of 210 block sums — one 256-thread block, two-level
//    shfl scan (replaces the 1-thread serial chain that cost 7.8us).
// ---------------------------------------------------------------------------
__global__ void k_scan() {
    __shared__ int ws[8];
    int t = threadIdx.x;          // 256 threads, 8 warps
    int lane = t & 31;
    int wid = t >> 5;
    int v = (t < NBLK) ? g_boff[t] : 0;

    // inclusive warp scan
    int inc = v;
    #pragma unroll
    for (int o = 1; o < 32; o <<= 1) {
        int nv = __shfl_up_sync(0xFFFFFFFFu, inc, o);
        if (lane >= o) inc += nv;
    }
    if (lane == 31) ws[wid] = inc;
    __syncthreads();
    if (wid == 0 && lane < 8) {
        int wv = ws[lane];
        #pragma unroll
        for (int o = 1; o < 8; o <<= 1) {
            int nv = __shfl_up_sync(0x000000FFu, wv, o);
            if (lane >= o) wv += nv;
        }
        ws[lane] = wv;  // inclusive warp totals
    }
    __syncthreads();

    int excl = (inc - v) + (wid > 0 ? ws[wid - 1] : 0);
    if (t < NBLK) g_boff[t] = excl;
}

// ---------------------------------------------------------------------------
// 5. Block-local exclusive scan -> seg id; write mean for seg < MAX_VOX
// ---------------------------------------------------------------------------
__global__ void k_write(float4* __restrict__ out4) {
    __shared__ int wsum[32];
    int b = blockIdx.x;
    int t = threadIdx.x;
    int lane = t & 31;
    int wid = t >> 5;
    int cell = b * CPB + t;
    int cnt = (cell < TOTAL_CELLS) ? g_vcnt[cell] : 0;
    int flag = cnt > 0;

    // inclusive warp scan of flags
    int v = flag;
    #pragma unroll
    for (int o = 1; o < 32; o <<= 1) {
        int nv = __shfl_up_sync(0xFFFFFFFFu, v, o);
        if (lane >= o) v += nv;
    }
    if (lane == 31) wsum[wid] = v;
    __syncthreads();
    if (wid == 0) {
        int w = wsum[lane];
        #pragma unroll
        for (int o = 1; o < 32; o <<= 1) {
            int nw = __shfl_up_sync(0xFFFFFFFFu, w, o);
            if (lane >= o) w += nw;
        }
        wsum[lane] = w;  // inclusive warp totals
    }
    __syncthreads();

    if (flag) {
        int excl = (v - flag) + (wid > 0 ? wsum[wid - 1] : 0);
        int seg = g_boff[b] + excl;
        if (seg < MAX_VOX) {
            float fc = (float)cnt;
            float4 s = g_vsum[cell];
            float4 r;
            r.x = __fdiv_rn(s.x, fc);
            r.y = __fdiv_rn(s.y, fc);
            r.z = __fdiv_rn(s.z, fc);
            r.w = __fdiv_rn(s.w, fc);
            out4[seg] = r;
        }
    }
}

// ---------------------------------------------------------------------------
extern "C" void kernel_launch(void* const* d_in, const int* in_sizes, int n_in,
                              void* d_out, int out_size) {
    const float* in = (const float*)d_in[0];
    float4* out4 = (float4*)d_out;
    int total = in_sizes[0];       // B * C * N = 4 * 4 * 200000
    int N = total / 16;            // points per batch (B=4, C=4)
    int P = total / 4;             // total points

    k_zero<<<512, 256>>>(out4);
    k_acc<<<(P + 255) / 256, 256>>>(in, N, P);
    k_count<<<NBLK, CPB>>>();
    k_scan<<<1, 256>>>();
    k_write<<<NBLK, CPB>>>(out4);
}